// round 17
// baseline (speedup 1.0000x reference)
#include <cuda_runtime.h>
#include <cuda_bf16.h>
#include <math.h>
#include <stdint.h>

#define BATCH 32
#define CDIM  512
#define NDIM  4096
#define TCL   72
#define KCL   64
#define NT1   128
#define NTILES 32            // 4096/128

// Scratch (static device globals; no runtime allocation)
__device__ __nv_bfloat16 g_a2h[(size_t)BATCH * KCL * NDIM];   // assign*invn, bf16
__device__ __nv_bfloat16 g_xb[(size_t)BATCH * CDIM * NDIM];   // x in bf16
__device__ __nv_bfloat16 g_wb[16 * 80 * 32];                  // W bf16 [chunk16][t(80)][c(32)]
__device__ float g_massp[(size_t)BATCH * NTILES * KCL];
__device__ float g_agg[(size_t)BATCH * KCL * CDIM];
__device__ int   g_sync[BATCH];                               // pass1-tiles-done per batch

__device__ __forceinline__ unsigned smem_u32(const void* p) {
    unsigned a;
    asm("{ .reg .u64 t; cvta.to.shared.u64 t, %1; cvt.u32.u64 %0, t; }" : "=r"(a) : "l"(p));
    return a;
}
__device__ __forceinline__ void ldsm_x4(uint32_t* r, unsigned addr) {
    asm volatile("ldmatrix.sync.aligned.m8n8.x4.shared.b16 {%0,%1,%2,%3}, [%4];"
                 : "=r"(r[0]), "=r"(r[1]), "=r"(r[2]), "=r"(r[3]) : "r"(addr));
}
__device__ __forceinline__ void ldsm_x4t(uint32_t* r, unsigned addr) {
    asm volatile("ldmatrix.sync.aligned.m8n8.x4.trans.shared.b16 {%0,%1,%2,%3}, [%4];"
                 : "=r"(r[0]), "=r"(r[1]), "=r"(r[2]), "=r"(r[3]) : "r"(addr));
}
__device__ __forceinline__ void mma_bf16(float* c, const uint32_t* a, const uint32_t* b) {
    asm volatile(
        "mma.sync.aligned.m16n8k16.row.col.f32.bf16.bf16.f32 "
        "{%0,%1,%2,%3},{%4,%5,%6,%7},{%8,%9},{%0,%1,%2,%3};"
        : "+f"(c[0]), "+f"(c[1]), "+f"(c[2]), "+f"(c[3])
        : "r"(a[0]), "r"(a[1]), "r"(a[2]), "r"(a[3]), "r"(b[0]), "r"(b[1]));
}
__device__ __forceinline__ void sts_v2(unsigned addr, __nv_bfloat162 p0, __nv_bfloat162 p1) {
    asm volatile("st.shared.v2.b32 [%0], {%1,%2};"
                 :: "r"(addr), "r"(*(unsigned*)&p0), "r"(*(unsigned*)&p1));
}
__device__ __forceinline__ void cpa16(unsigned dst, const void* src) {
    asm volatile("cp.async.cg.shared.global [%0], [%1], 16;" :: "r"(dst), "l"(src));
}
#define CP_COMMIT() asm volatile("cp.async.commit_group;")

// ---------------------------------------------------------------------------
// Pass 0w: W fp32 -> bf16 table (parallel) + g_sync reset (block 160).
// ---------------------------------------------------------------------------
__global__ __launch_bounds__(256) void pass0w(const float* __restrict__ conv_w)
{
    if (blockIdx.x == 160) {
        if (threadIdx.x < BATCH) g_sync[threadIdx.x] = 0;
        return;
    }
    const int i = blockIdx.x * 256 + threadIdx.x;   // 0..40959
    const int t = i >> 9, c = i & 511;
    float v = (t < TCL) ? conv_w[t * CDIM + c] : 0.0f;
    g_wb[(c >> 5) * 2560 + t * 32 + (c & 31)] = __float2bfloat16(v);
}

// ---------------------------------------------------------------------------
// Fused pass12: bids 0..1023 = pass1 role (batch-major: b=bid>>5, ntile=bid&31);
// bids 1024..1151 = pass2 role (spins on g_sync[b]==32 before consuming).
// pass2 reads a2/xb ONLY via cp.async.cg (L2-coherent) -> safe after spin.
// ---------------------------------------------------------------------------
#define P1_STG   23040u       // per stage: x 16384 (rows 512B) + W 6656 @ +16384
#define P1_WOFF  16384u
#define P1_XBUF  92160u       // 2 x (32c x 128n bf16, 256B rows, swz >>4)
#define P1_SSQS  108544u      // 4KB scratch
#define P1_INVN  112640u
#define P1_BIAS  113152u
#define P1_SMEM  113472
#define P1_LG    0u           // phase B: [128 n][84 t] fp32 (43008B)
#define P1_A2ST  43008u       // [64 k][128 n] bf16 (16384B)
#define P2_STG_SZ 24576u
#define P2_B_OFF  16384u

__global__ __launch_bounds__(256, 2) void pass12(const float* __restrict__ x,
                                                 const float* __restrict__ conv_b)
{
    extern __shared__ char sm[];
    const unsigned sb = smem_u32(sm);
    const int tid  = threadIdx.x;
    const int lane = tid & 31;
    const int wid  = tid >> 5;

    if (blockIdx.x < 1024) {
        // ===================== PASS1 ROLE ===================================
        const int b     = blockIdx.x >> 5;     // batch-major -> early completion
        const int ntile = blockIdx.x & 31;
        const int n0    = ntile * NT1;
        const int m0    = wid * 16;

        if (tid < 80) {
            float v = (tid < TCL) ? conv_b[tid] : 0.0f;
            *(float*)(sm + P1_BIAS + tid * 4) = v;
        }

        const float* xsrc = x + (size_t)b * CDIM * NDIM + n0;

#define P1_ISSUE(ST, CH) do {                                                  \
        unsigned _buf = sb + (unsigned)(ST) * P1_STG;                          \
        const float* _xs = xsrc + (size_t)(CH) * 32 * NDIM;                    \
        _Pragma("unroll")                                                      \
        for (int r = 0; r < 4; r++) {                                          \
            int idx = tid + 256 * r;                                           \
            int c = idx >> 5, q = idx & 31;                                    \
            cpa16(_buf + (unsigned)(c * 512 + q * 16),                         \
                  _xs + (size_t)c * NDIM + 4 * q);                             \
        }                                                                      \
        const __nv_bfloat16* _ws = g_wb + (CH) * 2560;                         \
        _Pragma("unroll")                                                      \
        for (int r = 0; r < 2; r++) {                                          \
            int idx = tid + 256 * r;                                           \
            if (idx < 320) {                                                   \
                int t = idx >> 2, pc = idx & 3;                                \
                cpa16(_buf + P1_WOFF + (unsigned)(t * 80 + pc * 16),           \
                      _ws + t * 32 + pc * 8);                                  \
            }                                                                  \
        }                                                                      \
    } while (0)

        P1_ISSUE(0, 0); CP_COMMIT();
        P1_ISSUE(1, 1); CP_COMMIT();
        P1_ISSUE(2, 2); CP_COMMIT();

        float acc[10][4];
        #pragma unroll
        for (int i = 0; i < 10; i++)
            #pragma unroll
            for (int j = 0; j < 4; j++) acc[i][j] = 0.0f;
        float ssq4[4] = {0.f, 0.f, 0.f, 0.f};

        const int cg = tid >> 5;
        const int gq = tid & 31;
        __nv_bfloat16* xbo = g_xb + (size_t)b * CDIM * NDIM + n0 + 4 * gq;

        for (int ch = 0; ch < 16; ch++) {
            asm volatile("cp.async.wait_group 2;" ::: "memory");
            __syncthreads();
            if (ch + 3 < 16) P1_ISSUE((ch + 3) & 3, ch + 3);
            CP_COMMIT();

            {   // convert
                const char* stg = sm + (unsigned)(ch & 3) * P1_STG;
                const unsigned xbuf = sb + P1_XBUF + (unsigned)(ch & 1) * 8192u;
                #pragma unroll
                for (int r = 0; r < 4; r++) {
                    int c = cg * 4 + r;
                    float4 v = *(const float4*)(stg + c * 512 + gq * 16);
                    ssq4[0] = fmaf(v.x, v.x, ssq4[0]);
                    ssq4[1] = fmaf(v.y, v.y, ssq4[1]);
                    ssq4[2] = fmaf(v.z, v.z, ssq4[2]);
                    ssq4[3] = fmaf(v.w, v.w, ssq4[3]);
                    __nv_bfloat162 h01 = __floats2bfloat162_rn(v.x, v.y);
                    __nv_bfloat162 h23 = __floats2bfloat162_rn(v.z, v.w);
                    unsigned off = (unsigned)(c * 256 + gq * 8);
                    sts_v2(xbuf + (off ^ ((off >> 4) & 0x70)), h01, h23);
                    uint2 u; u.x = *(unsigned*)&h01; u.y = *(unsigned*)&h23;
                    *(uint2*)(xbo + (size_t)(ch * 32 + c) * NDIM) = u;
                }
            }
            __syncthreads();

            const unsigned xbuf = sb + P1_XBUF + (unsigned)(ch & 1) * 8192u;
            const unsigned wst  = sb + (unsigned)(ch & 3) * P1_STG + P1_WOFF;
            #pragma unroll
            for (int ks = 0; ks < 2; ks++) {
                uint32_t a[4];
                {
                    int crow = ks * 16 + (lane & 7) + ((lane >> 4) & 1) * 8;
                    int ncol = m0 + ((lane >> 3) & 1) * 8;
                    unsigned off = (unsigned)(crow * 256 + ncol * 2);
                    ldsm_x4t(a, xbuf + (off ^ ((off >> 4) & 0x70)));
                }
                #pragma unroll
                for (int nb = 0; nb < 5; nb++) {
                    uint32_t bf[4];
                    int trow = nb * 16 + ((lane >> 4) & 1) * 8 + (lane & 7);
                    unsigned addr = wst + (unsigned)(trow * 80 + ks * 32
                                                     + ((lane >> 3) & 1) * 16);
                    ldsm_x4(bf, addr);
                    mma_bf16(acc[2 * nb],     a, &bf[0]);
                    mma_bf16(acc[2 * nb + 1], a, &bf[2]);
                }
            }
        }

        *(float4*)(sm + P1_SSQS + (unsigned)tid * 16) =
            make_float4(ssq4[0], ssq4[1], ssq4[2], ssq4[3]);
        __syncthreads();
        if (tid < 128) {
            const float* fs = (const float*)(sm + P1_SSQS);
            float s = 0.0f;
            #pragma unroll
            for (int w2 = 0; w2 < 8; w2++) s += fs[w2 * 128 + tid];
            ((float*)(sm + P1_INVN))[tid] = 1.0f / fmaxf(sqrtf(s), 1e-12f);
        }
        __syncthreads();

        {   // fragments -> logits [128 n][84 t]
            float* lg = (float*)(sm + P1_LG);
            const float* invn = (const float*)(sm + P1_INVN);
            const float* bias = (const float*)(sm + P1_BIAS);
            int r0 = m0 + (lane >> 2);
            float i0 = invn[r0], i1 = invn[r0 + 8];
            #pragma unroll
            for (int nb = 0; nb < 10; nb++) {
                int tc = nb * 8 + 2 * (lane & 3);
                float b0 = bias[tc], b1 = bias[tc + 1];
                lg[r0 * 84 + tc]           = acc[nb][0] * i0 + b0;
                lg[r0 * 84 + tc + 1]       = acc[nb][1] * i0 + b1;
                lg[(r0 + 8) * 84 + tc]     = acc[nb][2] * i1 + b0;
                lg[(r0 + 8) * 84 + tc + 1] = acc[nb][3] * i1 + b1;
            }
        }
        __syncthreads();

        if (tid < 128) {   // softmax per n; a2 bf16 staging
            float* row = (float*)(sm + P1_LG) + tid * 84;
            float invn_n = ((float*)(sm + P1_INVN))[tid];
            float mx = -1e30f;
            #pragma unroll 8
            for (int t = 0; t < TCL; t++) mx = fmaxf(mx, row[t]);
            float s = 0.0f;
            #pragma unroll 8
            for (int t = 0; t < TCL; t++) { float e = __expf(row[t] - mx); row[t] = e; s += e; }
            float inv_s = 1.0f / s;
            float a2s   = inv_s * invn_n;
            __nv_bfloat16* a2st = (__nv_bfloat16*)(sm + P1_A2ST);
            #pragma unroll 8
            for (int t = 0; t < KCL; t++) {
                float e = row[t];
                a2st[t * 128 + tid] = __float2bfloat16(e * a2s);
                row[t] = e * inv_s;
            }
        }
        __syncthreads();

        #pragma unroll
        for (int it = 0; it < 4; it++) {   // a2 writeout
            int idx = tid + 256 * it;
            int k = idx >> 4, q2 = idx & 15;
            *(uint4*)((char*)(g_a2h + ((size_t)(b * KCL + k)) * NDIM + n0) + 16 * q2)
                = *(const uint4*)(sm + P1_A2ST + k * 256 + 16 * q2);
        }

        {   // mass partials (parallel, deterministic)
            float* mp = (float*)(sm + P1_SSQS);
            const float* lg = (const float*)(sm + P1_LG);
            const int k = tid & 63, part = tid >> 6;
            float m = 0.0f;
            #pragma unroll 8
            for (int n = 0; n < 32; n++) m += lg[(part * 32 + n) * 84 + k];
            mp[part * 64 + k] = m;
        }
        __syncthreads();
        if (tid < KCL) {
            const float* mp = (const float*)(sm + P1_SSQS);
            g_massp[((size_t)b * NTILES + ntile) * KCL + tid] =
                mp[tid] + mp[64 + tid] + mp[128 + tid] + mp[192 + tid];
        }

        // signal: this batch-tile's a2/xb are globally visible
        __threadfence();
        __syncthreads();
        if (tid == 0) atomicAdd(&g_sync[b], 1);
#undef P1_ISSUE
    } else {
        // ===================== PASS2 ROLE ===================================
        const int idx = blockIdx.x - 1024;
        const int b   = idx >> 2;
        const int ct  = idx & 3;
        const int c0  = ct * 128;
        const int warp_m = (wid & 3) * 32;
        const int warp_n = (wid >> 2) * 32;

        // wait for all 32 pass1 tiles of this batch
        if (tid == 0) {
            while (atomicAdd(&g_sync[b], 0) < NTILES) __nanosleep(200);
            __threadfence();
        }
        __syncthreads();

        const __nv_bfloat16* xsrc = g_xb + ((size_t)b * CDIM + c0) * NDIM;
        const __nv_bfloat16* asrc = g_a2h + (size_t)b * KCL * NDIM;

#define P2_ISSUE(ST, CH) do {                                                  \
        unsigned _buf = sb + (unsigned)(ST) * P2_STG_SZ;                       \
        _Pragma("unroll")                                                      \
        for (int r = 0; r < 4; r++) {                                          \
            int g = tid + 256 * r; int row = g >> 3, c16 = g & 7;              \
            unsigned off = (unsigned)(row * 128 + c16 * 16);                   \
            cpa16(_buf + (off ^ ((off >> 3) & 0x70)),                          \
                  xsrc + (size_t)row * NDIM + (CH) * 64 + c16 * 8);            \
        }                                                                      \
        _Pragma("unroll")                                                      \
        for (int r = 0; r < 2; r++) {                                          \
            int g = tid + 256 * r; int k = g >> 3, c16 = g & 7;                \
            unsigned off = (unsigned)(k * 128 + c16 * 16);                     \
            cpa16(_buf + P2_B_OFF + (off ^ ((off >> 3) & 0x70)),               \
                  asrc + (size_t)k * NDIM + (CH) * 64 + c16 * 8);              \
        }                                                                      \
    } while (0)

        P2_ISSUE(0, 0); CP_COMMIT();
        P2_ISSUE(1, 1); CP_COMMIT();
        P2_ISSUE(2, 2); CP_COMMIT();

        float acc2[2][4][4];
        #pragma unroll
        for (int i = 0; i < 2; i++)
            #pragma unroll
            for (int j = 0; j < 4; j++)
                #pragma unroll
                for (int q = 0; q < 4; q++) acc2[i][j][q] = 0.0f;

        for (int ch = 0; ch < 64; ch++) {
            asm volatile("cp.async.wait_group 2;" ::: "memory");
            __syncthreads();
            if (ch + 3 < 64) P2_ISSUE((ch + 3) & 3, ch + 3);
            CP_COMMIT();

            const unsigned buf = sb + (unsigned)(ch & 3) * P2_STG_SZ;
            #pragma unroll
            for (int ks = 0; ks < 4; ks++) {
                uint32_t ah[2][4], bh2[2][4];
                #pragma unroll
                for (int mf = 0; mf < 2; mf++) {
                    unsigned off = (unsigned)((warp_m + mf * 16 + (lane & 15)) * 128
                                              + ks * 32 + (lane >> 4) * 16);
                    ldsm_x4(ah[mf], buf + (off ^ ((off >> 3) & 0x70)));
                }
                #pragma unroll
                for (int np = 0; np < 2; np++) {
                    unsigned off = (unsigned)((warp_n + np * 16 + (lane >> 4) * 8 + (lane & 7)) * 128
                                              + ks * 32 + ((lane >> 3) & 1) * 16);
                    ldsm_x4(bh2[np], buf + P2_B_OFF + (off ^ ((off >> 3) & 0x70)));
                }
                #pragma unroll
                for (int mf = 0; mf < 2; mf++)
                    #pragma unroll
                    for (int np = 0; np < 2; np++)
                        #pragma unroll
                        for (int h = 0; h < 2; h++)
                            mma_bf16(acc2[mf][np * 2 + h], ah[mf], &bh2[np][2 * h]);
            }
        }

        const int bbase = b * KCL;
        #pragma unroll
        for (int mf = 0; mf < 2; mf++) {
            int row = c0 + warp_m + mf * 16 + (lane >> 2);
            #pragma unroll
            for (int nf = 0; nf < 4; nf++) {
                int k = warp_n + nf * 8 + (lane & 3) * 2;
                float* g0 = g_agg + (size_t)(bbase + k) * CDIM + row;
                g0[0]        = acc2[mf][nf][0];
                g0[CDIM]     = acc2[mf][nf][1];
                g0[8]        = acc2[mf][nf][2];
                g0[CDIM + 8] = acc2[mf][nf][3];
            }
        }
#undef P2_ISSUE
    }
}

// ---------------------------------------------------------------------------
// Pass 3: v = agg - centroid*mass; out = v/(max(||v||,eps)*8)
// (attention, ghost weighting and global norm cancel algebraically)
// ---------------------------------------------------------------------------
__global__ __launch_bounds__(128) void pass3(const float* __restrict__ centroids,
                                             float* __restrict__ out)
{
    const int k   = blockIdx.x;
    const int b   = blockIdx.y;
    const int tid = threadIdx.x;

    __shared__ float s_mass;
    __shared__ float s_red[4];

    if (tid == 0) {
        float m = 0.0f;
        #pragma unroll
        for (int t = 0; t < NTILES; t++) m += g_massp[((size_t)b * NTILES + t) * KCL + k];
        s_mass = m;
    }
    __syncthreads();
    const float mass = s_mass;

    float v[4];
    float ssq = 0.0f;
    #pragma unroll
    for (int j = 0; j < 4; j++) {
        int c = tid + 128 * j;
        float val = g_agg[((size_t)b * KCL + k) * CDIM + c] - centroids[k * CDIM + c] * mass;
        v[j] = val;
        ssq = fmaf(val, val, ssq);
    }
    #pragma unroll
    for (int o = 16; o > 0; o >>= 1) ssq += __shfl_xor_sync(0xffffffffu, ssq, o);
    if ((tid & 31) == 0) s_red[tid >> 5] = ssq;
    __syncthreads();
    float tot = s_red[0] + s_red[1] + s_red[2] + s_red[3];
    float scale = 1.0f / (fmaxf(sqrtf(tot), 1e-12f) * 8.0f);
    #pragma unroll
    for (int j = 0; j < 4; j++)
        out[((size_t)b * KCL + k) * CDIM + tid + 128 * j] = v[j] * scale;
}

// ---------------------------------------------------------------------------
extern "C" void kernel_launch(void* const* d_in, const int* in_sizes, int n_in,
                              void* d_out, int out_size)
{
    const float* x         = (const float*)d_in[0];
    const float* centroids = (const float*)d_in[1];
    const float* conv_w    = (const float*)d_in[2];
    const float* conv_b    = (const float*)d_in[3];
    float* out = (float*)d_out;

    cudaFuncSetAttribute(pass12, cudaFuncAttributeMaxDynamicSharedMemorySize, P1_SMEM);

    pass0w<<<161, 256>>>(conv_w);
    pass12<<<1152, 256, P1_SMEM>>>(x, conv_b);
    pass3<<<dim3(KCL, BATCH), 128>>>(centroids, out);
}